// round 2
// baseline (speedup 1.0000x reference)
#include <cuda_runtime.h>

#define B_ 4
#define C_ 256
#define N_ 4096
#define CI_ 32
#define QKV_PITCH 320

// 20 MB scratch for fused [V | Q | K] projection, row-major per position:
// g_qkv[b][n][0:256]=V row, [256:288]=Q row, [288:320]=K row
__device__ float g_qkv[(size_t)B_ * N_ * QKV_PITCH];

// ---------------------------------------------------------------------------
// Kernel 1: QKV projection.  out[b,n,j] = sum_c W[j,c] * x[b,c,n]
// GEMM per batch: M=4096 (n) x N=384 (j padded, 320 real) x K=256 (c)
// ---------------------------------------------------------------------------
__global__ __launch_bounds__(256) void qkv_proj_kernel(
    const float* __restrict__ x, const float* __restrict__ wv,
    const float* __restrict__ wq, const float* __restrict__ wk)
{
    const int b  = blockIdx.z;
    const int nb = blockIdx.x * 128;   // n tile base
    const int j0 = blockIdx.y * 128;   // j tile base (0,128,256)
    const int tid = threadIdx.x;
    const int tyy = tid >> 4;          // 0..15 (row group)
    const int txx = tid & 15;          // 0..15 (col group)

    __shared__ float xs[16][128];      // x^T tile: xs[k][n]
    __shared__ float ws[16][132];      // W tile:  ws[k][j] (padded pitch)

    float acc[8][8];
#pragma unroll
    for (int i = 0; i < 8; i++)
#pragma unroll
        for (int j = 0; j < 8; j++) acc[i][j] = 0.f;

    const float* xb = x + (size_t)b * C_ * N_;

    for (int c0 = 0; c0 < C_; c0 += 16) {
        // load x tile (coalesced float4 along n)
#pragma unroll
        for (int w = 0; w < 2; w++) {
            int f4 = tid + w * 256;            // 0..511
            int k  = f4 >> 5, n4 = f4 & 31;
            float4 v = *(const float4*)(xb + (size_t)(c0 + k) * N_ + nb + n4 * 4);
            *(float4*)(&xs[k][n4 * 4]) = v;
        }
        // load W tile (stacked wv/wq/wk, zero-pad j>=320)
#pragma unroll
        for (int it = 0; it < 8; it++) {
            int jl = (tid >> 4) + it * 16;     // 0..127
            int k  = tid & 15;
            int j  = j0 + jl;
            int c  = c0 + k;
            float val = 0.f;
            if (j < 256)      val = wv[j * C_ + c];
            else if (j < 288) val = wq[(j - 256) * C_ + c];
            else if (j < 320) val = wk[(j - 288) * C_ + c];
            ws[k][jl] = val;
        }
        __syncthreads();
#pragma unroll
        for (int k = 0; k < 16; k++) {
            float a[8], bb[8];
            *(float4*)&a[0]  = *(const float4*)&xs[k][tyy * 4];
            *(float4*)&a[4]  = *(const float4*)&xs[k][64 + tyy * 4];
            *(float4*)&bb[0] = *(const float4*)&ws[k][txx * 4];
            *(float4*)&bb[4] = *(const float4*)&ws[k][64 + txx * 4];
#pragma unroll
            for (int i = 0; i < 8; i++)
#pragma unroll
                for (int j = 0; j < 8; j++)
                    acc[i][j] = fmaf(a[i], bb[j], acc[i][j]);
        }
        __syncthreads();
    }

    float* qout = g_qkv + (size_t)b * N_ * QKV_PITCH;
#pragma unroll
    for (int i = 0; i < 8; i++) {
        int row = nb + ((i < 4) ? (tyy * 4 + i) : (64 + tyy * 4 + i - 4));
#pragma unroll
        for (int cb = 0; cb < 2; cb++) {
            int j = j0 + cb * 64 + txx * 4;
            if (j < QKV_PITCH) {
                float4 v = make_float4(acc[i][cb * 4 + 0], acc[i][cb * 4 + 1],
                                       acc[i][cb * 4 + 2], acc[i][cb * 4 + 3]);
                *(float4*)(qout + (size_t)row * QKV_PITCH + j) = v;
            }
        }
    }
}

// ---------------------------------------------------------------------------
// Kernel 2: fused flash attention (distance-divided scores, online softmax,
// P@V) + BatchNorm + ReLU + residual epilogue.
// One CTA = one batch b, one 64-row query tile. 256 threads.
// Thread (ty=warp 0..7, tx=lane): rows r = ty*8+i (i<8),
// cols c in {tx*4..tx*4+3} U {128+tx*4..+3}.  acc: 8x8 fp32 regs.
// ---------------------------------------------------------------------------
#define TQ 64
#define TM 64

// shared memory layout (in floats)
#define QS_OFF 0                      // Qs[64][32]
#define KS_OFF 2048                   // Ks[64][36]   (padded)
#define VS_OFF (2048 + 2304)          // Vs[64][260]  (padded; reused as sacc)
#define PT_OFF (VS_OFF + 16640)       // Pt[64][72]   (P transposed [m][r])
#define LS_OFF (PT_OFF + 4608)        // ls[64]
#define SMEM_FLOATS (LS_OFF + 64)
#define SMEM_BYTES (SMEM_FLOATS * 4)  // 102,656 B -> 2 CTAs/SM

__global__ __launch_bounds__(256, 2) void attn_kernel(
    const float* __restrict__ x, const float* __restrict__ gamma,
    const float* __restrict__ beta, const float* __restrict__ mean,
    const float* __restrict__ var, float* __restrict__ out)
{
    extern __shared__ float sm[];
    float* Qs = sm + QS_OFF;
    float* Ks = sm + KS_OFF;
    float* Vs = sm + VS_OFF;
    float* Pt = sm + PT_OFF;
    float* ls = sm + LS_OFF;

    const int b   = blockIdx.y;
    const int qb  = blockIdx.x * TQ;
    const int tid = threadIdx.x;
    const int ty  = tid >> 5;   // warp id 0..7
    const int tx  = tid & 31;   // lane
    const float* qkv = g_qkv + (size_t)b * N_ * QKV_PITCH;

    // load Q tile [64][32]
#pragma unroll
    for (int w = 0; w < 2; w++) {
        int f4 = tid + w * 256;
        int row = f4 >> 3, c4 = f4 & 7;
        float4 v = *(const float4*)(qkv + (size_t)(qb + row) * QKV_PITCH + 256 + c4 * 4);
        *(float4*)(Qs + row * 32 + c4 * 4) = v;
    }

    float acc[8][8];
#pragma unroll
    for (int i = 0; i < 8; i++)
#pragma unroll
        for (int j = 0; j < 8; j++) acc[i][j] = 0.f;

    float mrow[8], lrow[8];
#pragma unroll
    for (int i = 0; i < 8; i++) { mrow[i] = -1e30f; lrow[i] = 0.f; }

    for (int kb = 0; kb < N_; kb += TM) {
        __syncthreads();   // previous P@V done reading Ks/Vs/Pt
        // load K tile [64][32] -> Ks pitch 36
#pragma unroll
        for (int w = 0; w < 2; w++) {
            int f4 = tid + w * 256;
            int row = f4 >> 3, c4 = f4 & 7;
            float4 v = *(const float4*)(qkv + (size_t)(kb + row) * QKV_PITCH + 288 + c4 * 4);
            *(float4*)(Ks + row * 36 + c4 * 4) = v;
        }
        // load V tile [64][256] -> Vs pitch 260
#pragma unroll
        for (int w = 0; w < 16; w++) {
            int f4 = tid + w * 256;
            int row = f4 >> 6, c4 = f4 & 63;
            float4 v = *(const float4*)(qkv + (size_t)(kb + row) * QKV_PITCH + c4 * 4);
            *(float4*)(Vs + row * 260 + c4 * 4) = v;
        }
        __syncthreads();

        // ---- S = Q K^T for this thread's 8 rows x 2 key cols (m=tx, tx+32)
        float s0[8], s1[8];
#pragma unroll
        for (int i = 0; i < 8; i++) { s0[i] = 0.f; s1[i] = 0.f; }
#pragma unroll
        for (int c4 = 0; c4 < 8; c4++) {
            float4 k0 = *(const float4*)(Ks + tx * 36 + c4 * 4);
            float4 k1 = *(const float4*)(Ks + (tx + 32) * 36 + c4 * 4);
#pragma unroll
            for (int i = 0; i < 8; i++) {
                float4 q = *(const float4*)(Qs + (ty * 8 + i) * 32 + c4 * 4);
                s0[i] = fmaf(q.x, k0.x, fmaf(q.y, k0.y, fmaf(q.z, k0.z, fmaf(q.w, k0.w, s0[i]))));
                s1[i] = fmaf(q.x, k1.x, fmaf(q.y, k1.y, fmaf(q.z, k1.z, fmaf(q.w, k1.w, s1[i]))));
            }
        }

        // ---- divide by distance, online softmax, write P^T
        const int m0 = kb + tx, m1 = kb + tx + 32;
        const int m0y = m0 >> 6, m0x = m0 & 63;
        const int m1y = m1 >> 6, m1x = m1 & 63;
#pragma unroll
        for (int i = 0; i < 8; i++) {
            const int r  = qb + ty * 8 + i;
            const int ry = r >> 6, rx = r & 63;
            int dy0 = ry - m0y, dx0 = rx - m0x;
            int dy1 = ry - m1y, dx1 = rx - m1x;
            float d0 = sqrtf((float)(dy0 * dy0 + dx0 * dx0)) + 1.0f;
            float d1 = sqrtf((float)(dy1 * dy1 + dx1 * dx1)) + 1.0f;
            s0[i] /= d0;
            s1[i] /= d1;

            float ml = fmaxf(s0[i], s1[i]);
#pragma unroll
            for (int off = 16; off; off >>= 1)
                ml = fmaxf(ml, __shfl_xor_sync(0xffffffffu, ml, off));
            float mnew = fmaxf(mrow[i], ml);
            float p0 = __expf(s0[i] - mnew);
            float p1 = __expf(s1[i] - mnew);
            float psum = p0 + p1;
#pragma unroll
            for (int off = 16; off; off >>= 1)
                psum += __shfl_xor_sync(0xffffffffu, psum, off);
            float scale = __expf(mrow[i] - mnew);
            lrow[i] = lrow[i] * scale + psum;
            mrow[i] = mnew;
            if (scale != 1.0f) {
#pragma unroll
                for (int j = 0; j < 8; j++) acc[i][j] *= scale;
            }
            Pt[tx * 72 + ty * 8 + i]        = p0;
            Pt[(tx + 32) * 72 + ty * 8 + i] = p1;
        }
        __syncthreads();

        // ---- P @ V : per m, 4x LDS.128 feeding 64 FFMA
#pragma unroll 2
        for (int m = 0; m < TM; m++) {
            float4 pa = *(const float4*)(Pt + m * 72 + ty * 8);
            float4 pb = *(const float4*)(Pt + m * 72 + ty * 8 + 4);
            float4 va = *(const float4*)(Vs + m * 260 + tx * 4);
            float4 vb = *(const float4*)(Vs + m * 260 + 128 + tx * 4);
            float p[8]  = {pa.x, pa.y, pa.z, pa.w, pb.x, pb.y, pb.z, pb.w};
            float vv[8] = {va.x, va.y, va.z, va.w, vb.x, vb.y, vb.z, vb.w};
#pragma unroll
            for (int i = 0; i < 8; i++)
#pragma unroll
                for (int j = 0; j < 8; j++)
                    acc[i][j] = fmaf(p[i], vv[j], acc[i][j]);
        }
    }

    // ---- epilogue: transpose through smem, BN + ReLU + residual, coalesced out
    __syncthreads();
#pragma unroll
    for (int i = 0; i < 8; i++) {
        int r = ty * 8 + i;
        *(float4*)(Vs + r * 260 + tx * 4)       = make_float4(acc[i][0], acc[i][1], acc[i][2], acc[i][3]);
        *(float4*)(Vs + r * 260 + 128 + tx * 4) = make_float4(acc[i][4], acc[i][5], acc[i][6], acc[i][7]);
        if (tx == 0) ls[r] = lrow[i];
    }
    __syncthreads();

    const int nl = tid & 63;          // local row (n within tile)
    const int cg = tid >> 6;          // channel group 0..3
    const float rl = 1.0f / ls[nl];
    const size_t obase = (size_t)b * C_ * N_ + qb + nl;
    for (int c = cg; c < C_; c += 4) {
        float inv = gamma[c] * rsqrtf(var[c] + 1e-5f);
        float add = fmaf(-mean[c], inv, beta[c]);
        float y   = Vs[nl * 260 + c] * rl;
        float val = fmaf(y, inv, add);
        val = fmaxf(val, 0.0f) + x[obase + (size_t)c * N_];
        out[obase + (size_t)c * N_] = val;
    }
}

// ---------------------------------------------------------------------------
extern "C" void kernel_launch(void* const* d_in, const int* in_sizes, int n_in,
                              void* d_out, int out_size)
{
    (void)in_sizes; (void)n_in; (void)out_size;
    const float* x     = (const float*)d_in[0];
    const float* wv    = (const float*)d_in[1];
    const float* wq    = (const float*)d_in[2];
    const float* wk    = (const float*)d_in[3];
    const float* gamma = (const float*)d_in[4];
    const float* beta  = (const float*)d_in[5];
    const float* mean  = (const float*)d_in[6];
    const float* var   = (const float*)d_in[7];
    // d_in[8] = distance: recomputed analytically in-kernel, not read.
    float* out = (float*)d_out;

    qkv_proj_kernel<<<dim3(N_ / 128, 3, B_), 256>>>(x, wv, wq, wk);

    cudaFuncSetAttribute(attn_kernel, cudaFuncAttributeMaxDynamicSharedMemorySize, SMEM_BYTES);
    attn_kernel<<<dim3(N_ / TQ, B_), 256, SMEM_BYTES>>>(x, gamma, beta, mean, var, out);
}

// round 5
// speedup vs baseline: 6.1489x; 6.1489x over previous
#include <cuda_runtime.h>
#include <cuda_fp16.h>
#include <stdint.h>

#define B_ 4
#define C_ 256
#define N_ 4096

// ---------------- device scratch ----------------
__device__ __align__(256) __half g_v16[(size_t)B_ * N_ * C_];   // V fp16 [b][n][c]
__device__ __align__(256) __half g_q  [(size_t)B_ * N_ * 64];   // [b][n][qh32|ql32]
__device__ __align__(256) __half g_k  [(size_t)B_ * N_ * 64];   // [b][n][kh32|kl32]
__device__ __align__(256) __half g_qt [(size_t)B_ * 64 * 4096]; // swizzled 8KB q-tiles
__device__ __align__(256) __half g_kt [(size_t)B_ * 64 * 4096]; // swizzled 8KB k-tiles
__device__ __align__(256) __half g_vt [(size_t)B_ * 64 * 16384];// swizzled 32KB V^T tiles [c][n]

// ---------------- asm helpers ----------------
__device__ __forceinline__ uint32_t smem_u32(const void* p) {
    uint32_t a;
    asm("{ .reg .u64 t; cvta.to.shared.u64 t, %1; cvt.u32.u64 %0, t; }" : "=r"(a) : "l"(p));
    return a;
}
__device__ __forceinline__ void ldsm4(uint32_t* r, uint32_t a) {
    asm volatile("ldmatrix.sync.aligned.m8n8.x4.shared.b16 {%0,%1,%2,%3}, [%4];"
        : "=r"(r[0]), "=r"(r[1]), "=r"(r[2]), "=r"(r[3]) : "r"(a));
}
__device__ __forceinline__ void mma16816(float* c, const uint32_t* a, const uint32_t* b) {
    asm volatile("mma.sync.aligned.m16n8k16.row.col.f32.f16.f16.f32 "
        "{%0,%1,%2,%3}, {%4,%5,%6,%7}, {%8,%9}, {%0,%1,%2,%3};"
        : "+f"(c[0]), "+f"(c[1]), "+f"(c[2]), "+f"(c[3])
        : "r"(a[0]), "r"(a[1]), "r"(a[2]), "r"(a[3]), "r"(b[0]), "r"(b[1]));
}
__device__ __forceinline__ uint32_t pk(float lo, float hi) {
    uint32_t r;
    asm("cvt.rn.f16x2.f32 %0, %1, %2;" : "=r"(r) : "f"(hi), "f"(lo));
    return r;
}
#define MBAR_INIT(m, c) \
    asm volatile("mbarrier.init.shared.b64 [%0], %1;" :: "r"((uint32_t)(m)), "r"((uint32_t)(c)) : "memory")
#define MBAR_EXPECT_TX(m, b) \
    asm volatile("mbarrier.arrive.expect_tx.shared.b64 _, [%0], %1;" :: "r"((uint32_t)(m)), "r"((uint32_t)(b)) : "memory")
#define MBAR_WAIT(m, ph) do { \
    uint32_t _m = (uint32_t)(m), _p = (uint32_t)(ph), _d; \
    asm volatile("{\n\t.reg .pred p;\n\t" \
        "mbarrier.try_wait.parity.acquire.cta.shared::cta.b64 p, [%1], %2;\n\tselp.b32 %0,1,0,p;\n\t}" \
        : "=r"(_d) : "r"(_m), "r"(_p) : "memory"); \
    if (!_d) { asm volatile("{\n\t.reg .pred P1;\n\tWL_%=:\n\t" \
        "mbarrier.try_wait.parity.acquire.cta.shared::cta.b64 P1, [%0], %1, 0x989680;\n\t" \
        "@P1 bra.uni WD_%=;\n\tbra.uni WL_%=;\n\tWD_%=:\n\t}" :: "r"(_m), "r"(_p) : "memory"); } \
} while (0)
__device__ __forceinline__ void bulk_g2s(uint32_t dst, const void* src, uint32_t bytes, uint32_t mbar) {
    asm volatile("cp.async.bulk.shared::cluster.global.mbarrier::complete_tx::bytes [%0], [%1], %2, [%3];"
        :: "r"(dst), "l"(__cvta_generic_to_global(src)), "r"(bytes), "r"(mbar) : "memory");
}

// ---------------------------------------------------------------------------
// Kernel 1: QKV projection (FFMA, known-correct math from R1; new stores).
// ---------------------------------------------------------------------------
__global__ __launch_bounds__(256) void qkv_proj_kernel(
    const float* __restrict__ x, const float* __restrict__ wv,
    const float* __restrict__ wq, const float* __restrict__ wk)
{
    const int b = blockIdx.z, nb = blockIdx.x * 128, j0 = blockIdx.y * 128;
    const int tid = threadIdx.x, tyy = tid >> 4, txx = tid & 15;
    __shared__ float xs[16][128];
    __shared__ float ws[16][132];
    float acc[8][8];
#pragma unroll
    for (int i = 0; i < 8; i++)
#pragma unroll
        for (int j = 0; j < 8; j++) acc[i][j] = 0.f;
    const float* xb = x + (size_t)b * C_ * N_;

    for (int c0 = 0; c0 < C_; c0 += 16) {
#pragma unroll
        for (int w = 0; w < 2; w++) {
            int f4 = tid + w * 256, k = f4 >> 5, n4 = f4 & 31;
            *(float4*)(&xs[k][n4 * 4]) = *(const float4*)(xb + (size_t)(c0 + k) * N_ + nb + n4 * 4);
        }
#pragma unroll
        for (int it = 0; it < 8; it++) {
            int jl = (tid >> 4) + it * 16, k = tid & 15, j = j0 + jl, c = c0 + k;
            float v = 0.f;
            if (j < 256) v = wv[j * C_ + c];
            else if (j < 288) v = wq[(j - 256) * C_ + c];
            else if (j < 320) v = wk[(j - 288) * C_ + c];
            ws[k][jl] = v;
        }
        __syncthreads();
#pragma unroll
        for (int k = 0; k < 16; k++) {
            float a[8], bb[8];
            *(float4*)&a[0]  = *(const float4*)&xs[k][tyy * 4];
            *(float4*)&a[4]  = *(const float4*)&xs[k][64 + tyy * 4];
            *(float4*)&bb[0] = *(const float4*)&ws[k][txx * 4];
            *(float4*)&bb[4] = *(const float4*)&ws[k][64 + txx * 4];
#pragma unroll
            for (int i = 0; i < 8; i++)
#pragma unroll
                for (int j = 0; j < 8; j++) acc[i][j] = fmaf(a[i], bb[j], acc[i][j]);
        }
        __syncthreads();
    }

    if (j0 < 256) {
        __half* vo = g_v16 + (size_t)b * N_ * C_;
#pragma unroll
        for (int i = 0; i < 8; i++) {
            int row = nb + ((i < 4) ? (tyy * 4 + i) : (64 + tyy * 4 + i - 4));
#pragma unroll
            for (int g = 0; g < 2; g++) {
                int j = j0 + g * 64 + txx * 4;
                __half2 h01 = __floats2half2_rn(acc[i][g*4+0], acc[i][g*4+1]);
                __half2 h23 = __floats2half2_rn(acc[i][g*4+2], acc[i][g*4+3]);
                *(__half2*)(vo + (size_t)row * C_ + j)     = h01;
                *(__half2*)(vo + (size_t)row * C_ + j + 2) = h23;
            }
        }
    } else {
        // j0 == 256: cols txx*4+jj (jj<4): 0..31 -> Q, 32..63 -> K. jj>=4 unused.
        __half* qo = g_q + (size_t)b * N_ * 64;
        __half* ko = g_k + (size_t)b * N_ * 64;
#pragma unroll
        for (int i = 0; i < 8; i++) {
            int row = nb + ((i < 4) ? (tyy * 4 + i) : (64 + tyy * 4 + i - 4));
            int q4 = txx * 4;
            __half hi[4], lo[4];
#pragma unroll
            for (int jj = 0; jj < 4; jj++) {
                float a = acc[i][jj];
                __half h = __float2half_rn(a);
                hi[jj] = h;
                lo[jj] = __float2half_rn(a - __half2float(h));
            }
            __half* base = (q4 < 32) ? (qo + (size_t)row * 64 + q4)
                                     : (ko + (size_t)row * 64 + (q4 - 32));
            *(uint2*)base        = *(uint2*)hi;
            *(uint2*)(base + 32) = *(uint2*)lo;
        }
    }
}

// ---------------------------------------------------------------------------
// Kernel 2: retile Q/K rows into contiguous swizzled 8KB tiles.
// ---------------------------------------------------------------------------
__global__ __launch_bounds__(256) void retile_qk_kernel() {
    const int t = blockIdx.x, which = blockIdx.y, b = blockIdx.z;
    const __half* src = (which ? g_k : g_q) + ((size_t)b * N_ + t * 64) * 64;
    char* dst = (char*)((which ? g_kt : g_qt) + ((size_t)(b * 64 + t)) * 4096);
#pragma unroll
    for (int it = 0; it < 2; it++) {
        int e = threadIdx.x + it * 256;        // 0..511 chunks of 16B
        int r = e >> 3, c16 = (e & 7) * 16;
        uint4 v = *(const uint4*)((const char*)(src + (size_t)r * 64) + c16);
        *(uint4*)(dst + r * 128 + (c16 ^ ((r & 7) << 4))) = v;
    }
}

// ---------------------------------------------------------------------------
// Kernel 3: V transpose into swizzled 32KB tiles [c][n] per key-tile.
// ---------------------------------------------------------------------------
__global__ __launch_bounds__(256) void vtrans_kernel() {
    const int t = blockIdx.x, cb = blockIdx.y * 64, b = blockIdx.z;
    __shared__ __half ts[64][72];
    const __half* src = g_v16 + ((size_t)b * N_ + t * 64) * C_ + cb;
#pragma unroll
    for (int it = 0; it < 2; it++) {
        int e = threadIdx.x + it * 256;        // 512 chunks of 8 halves
        int n = e >> 3, c8 = (e & 7) * 8;
        *(uint4*)&ts[n][c8] = *(const uint4*)(src + (size_t)n * C_ + c8);
    }
    __syncthreads();
    char* dst = (char*)(g_vt + ((size_t)(b * 64 + t)) * 16384);
#pragma unroll
    for (int it = 0; it < 16; it++) {
        int e = threadIdx.x + it * 256;        // 4096 elements
        int cl = e >> 6, n = e & 63;
        int c = cb + cl;
        *(__half*)(dst + c * 128 + ((n * 2) ^ ((c & 7) << 4))) = ts[n][cl];
    }
}

// ---------------------------------------------------------------------------
// Kernel 4: HMMA flash attention + BN/ReLU/residual.
// CTA = 64 q rows (qt), 8 warps: wm = w&3 (16-row band), wc = w>>2 (128-col half of Y).
// ---------------------------------------------------------------------------
#define OFF_RDT 0
#define OFF_Q   16384
#define OFF_K   24576      /* 2 x 8192 */
#define OFF_V   40960      /* 2 x 32768 */
#define OFF_BAR 106496
#define SMEM_SZ 106624

__global__ __launch_bounds__(256, 1) void attn_kernel(
    const float* __restrict__ x, const float* __restrict__ gamma,
    const float* __restrict__ beta, const float* __restrict__ mean,
    const float* __restrict__ var, float* __restrict__ out)
{
    extern __shared__ char smc[];
    float* rdt = (float*)(smc + OFF_RDT);
    const uint32_t sb = smem_u32(smc);
    const int tid = threadIdx.x, w = tid >> 5, lane = tid & 31;
    const int wm = w & 3, wc = w >> 2;
    const int b = blockIdx.y, qt = blockIdx.x, qb = qt * 64;

    // distance table 1/(sqrt(dy^2+dx^2)+1)
    for (int i = tid; i < 4096; i += 256) {
        int dy = i >> 6, dx = i & 63;
        rdt[i] = 1.0f / (sqrtf((float)(dy * dy + dx * dx)) + 1.0f);
    }
    // Q tile copy (pre-swizzled 8KB)
    {
        const uint4* qsrc = (const uint4*)(g_qt + ((size_t)(b * 64 + qt)) * 4096);
        uint4* qdst = (uint4*)(smc + OFF_Q);
#pragma unroll
        for (int it = 0; it < 2; it++) qdst[tid + it * 256] = qsrc[tid + it * 256];
    }
    if (tid == 0) { MBAR_INIT(sb + OFF_BAR, 1); MBAR_INIT(sb + OFF_BAR + 8, 1); }
    __syncthreads();

    // Q A-frags (persistent): [hl][kstep][4]
    uint32_t qf[2][2][4];
#pragma unroll
    for (int hl = 0; hl < 2; hl++)
#pragma unroll
        for (int kk = 0; kk < 2; kk++) {
            int row = wm * 16 + (lane & 7) + ((lane & 8) ? 8 : 0);
            int colb = hl * 64 + kk * 32 + ((lane & 16) ? 16 : 0);
            ldsm4(qf[hl][kk], sb + OFF_Q + row * 128 + (colb ^ ((row & 7) << 4)));
        }

    const __half* kt = g_kt + (size_t)b * 64 * 4096;
    const __half* vt = g_vt + (size_t)b * 64 * 16384;

    // prologue: tile 0 into stage 0
    if (tid == 0) {
        MBAR_EXPECT_TX(sb + OFF_BAR, 40960);
        bulk_g2s(sb + OFF_K, kt, 8192, sb + OFF_BAR);
        bulk_g2s(sb + OFF_V, vt, 32768, sb + OFF_BAR);
    }

    float y[16][4];
#pragma unroll
    for (int i = 0; i < 16; i++)
#pragma unroll
        for (int j = 0; j < 4; j++) y[i][j] = 0.f;
    float mA = -1e30f, mB = -1e30f, lA = 0.f, lB = 0.f;

    const int rxA = wm * 16 + (lane >> 2), rxB = rxA + 8;
    const int c0 = 2 * (lane & 3);

    for (int t = 0; t < 64; t++) {
        // producer: stage for t+1 (buffer freed by trailing syncthreads of t-1)
        if (tid == 0 && t + 1 < 64) {
            uint32_t st = (t + 1) & 1;
            MBAR_EXPECT_TX(sb + OFF_BAR + st * 8, 40960);
            bulk_g2s(sb + OFF_K + st * 8192,  kt + (size_t)(t + 1) * 4096,  8192,  sb + OFF_BAR + st * 8);
            bulk_g2s(sb + OFF_V + st * 32768, vt + (size_t)(t + 1) * 16384, 32768, sb + OFF_BAR + st * 8);
        }
        MBAR_WAIT(sb + OFF_BAR + (t & 1) * 8, (t >> 1) & 1);

        const uint32_t bK = sb + OFF_K + (t & 1) * 8192;
        const uint32_t bV = sb + OFF_V + (t & 1) * 32768;

        // ---- GEMM1: S[16 x 64] = Qh*Kh + Ql*Kh + Qh*Kl
        float s[8][4];
#pragma unroll
        for (int i = 0; i < 8; i++)
#pragma unroll
            for (int j = 0; j < 4; j++) s[i][j] = 0.f;
#pragma unroll
        for (int kk = 0; kk < 2; kk++)
#pragma unroll
            for (int jp = 0; jp < 4; jp++) {
                int row = jp * 16 + (lane & 7) + ((lane & 16) ? 8 : 0);
                int colb = kk * 32 + ((lane & 8) ? 16 : 0);
                uint32_t bh[4], bl[4];
                ldsm4(bh, bK + row * 128 + (colb ^ ((row & 7) << 4)));
                ldsm4(bl, bK + row * 128 + ((colb + 64) ^ ((row & 7) << 4)));
                mma16816(s[jp*2],   qf[0][kk], bh);
                mma16816(s[jp*2+1], qf[0][kk], bh + 2);
                mma16816(s[jp*2],   qf[1][kk], bh);
                mma16816(s[jp*2+1], qf[1][kk], bh + 2);
                mma16816(s[jp*2],   qf[0][kk], bl);
                mma16816(s[jp*2+1], qf[0][kk], bl + 2);
            }

        // ---- softmax (distance factor; online max for fp16-safe P)
        const float* rdtp = rdt + ((qt > t) ? (qt - t) : (t - qt)) * 64;
        float tmA = -1e30f, tmB = -1e30f;
#pragma unroll
        for (int j = 0; j < 8; j++) {
            int c = j * 8 + c0;
            int d0 = rxA - c;     d0 = d0 < 0 ? -d0 : d0;
            int d1 = rxA - c - 1; d1 = d1 < 0 ? -d1 : d1;
            int d2 = rxB - c;     d2 = d2 < 0 ? -d2 : d2;
            int d3 = rxB - c - 1; d3 = d3 < 0 ? -d3 : d3;
            s[j][0] *= rdtp[d0];
            s[j][1] *= rdtp[d1];
            s[j][2] *= rdtp[d2];
            s[j][3] *= rdtp[d3];
            tmA = fmaxf(tmA, fmaxf(s[j][0], s[j][1]));
            tmB = fmaxf(tmB, fmaxf(s[j][2], s[j][3]));
        }
        tmA = fmaxf(tmA, __shfl_xor_sync(0xffffffffu, tmA, 1));
        tmA = fmaxf(tmA, __shfl_xor_sync(0xffffffffu, tmA, 2));
        tmB = fmaxf(tmB, __shfl_xor_sync(0xffffffffu, tmB, 1));
        tmB = fmaxf(tmB, __shfl_xor_sync(0xffffffffu, tmB, 2));
        float mnA = fmaxf(mA, tmA), mnB = fmaxf(mB, tmB);
        float scA = __expf(mA - mnA), scB = __expf(mB - mnB);
        mA = mnA; mB = mnB;
        if (!__all_sync(0xffffffffu, (scA == 1.f) && (scB == 1.f))) {
            lA *= scA; lB *= scB;
#pragma unroll
            for (int nt = 0; nt < 16; nt++) {
                y[nt][0] *= scA; y[nt][1] *= scA;
                y[nt][2] *= scB; y[nt][3] *= scB;
            }
        }
        float sumA = 0.f, sumB = 0.f;
        uint32_t pf[4][4];
#pragma unroll
        for (int j = 0; j < 8; j++) {
            float p0 = __expf(s[j][0] - mnA), p1 = __expf(s[j][1] - mnA);
            float p2 = __expf(s[j][2] - mnB), p3 = __expf(s[j][3] - mnB);
            sumA += p0 + p1; sumB += p2 + p3;
            int kk = j >> 1;
            if (!(j & 1)) { pf[kk][0] = pk(p0, p1); pf[kk][1] = pk(p2, p3); }
            else          { pf[kk][2] = pk(p0, p1); pf[kk][3] = pk(p2, p3); }
        }
        sumA += __shfl_xor_sync(0xffffffffu, sumA, 1);
        sumA += __shfl_xor_sync(0xffffffffu, sumA, 2);
        sumB += __shfl_xor_sync(0xffffffffu, sumB, 1);
        sumB += __shfl_xor_sync(0xffffffffu, sumB, 2);
        lA += sumA; lB += sumB;

        // ---- GEMM2: Y[16 x 128] += P * V^T
#pragma unroll
        for (int kk = 0; kk < 4; kk++)
#pragma unroll
            for (int np = 0; np < 8; np++) {
                int row = wc * 128 + np * 16 + (lane & 7) + ((lane & 16) ? 8 : 0);
                int colb = kk * 32 + ((lane & 8) ? 16 : 0);
                uint32_t bv[4];
                ldsm4(bv, bV + row * 128 + (colb ^ ((row & 7) << 4)));
                mma16816(y[np*2],   pf[kk], bv);
                mma16816(y[np*2+1], pf[kk], bv + 2);
            }
        __syncthreads();   // all warps done with stage (t&1) before reload at t+1
    }

    // ---- epilogue: normalize, transpose via smem, BN + ReLU + residual
    float* Ys = (float*)smc;     // [64][257]
    float rA = 1.f / lA, rB = 1.f / lB;
#pragma unroll
    for (int nt = 0; nt < 16; nt++) {
        int c = wc * 128 + nt * 8 + c0;
        Ys[rxA * 257 + c]     = y[nt][0] * rA;
        Ys[rxA * 257 + c + 1] = y[nt][1] * rA;
        Ys[rxB * 257 + c]     = y[nt][2] * rB;
        Ys[rxB * 257 + c + 1] = y[nt][3] * rB;
    }
    __syncthreads();
    const int n = tid & 63, cg = tid >> 6;
    for (int it = 0; it < 64; it++) {
        int c = it * 4 + cg;
        float inv = gamma[c] * rsqrtf(var[c] + 1e-5f);
        float add = fmaf(-mean[c], inv, beta[c]);
        size_t idx = ((size_t)b * C_ + c) * N_ + qb + n;
        float yv = Ys[n * 257 + c];
        out[idx] = fmaxf(fmaf(yv, inv, add), 0.f) + x[idx];
    }
}

// ---------------------------------------------------------------------------
extern "C" void kernel_launch(void* const* d_in, const int* in_sizes, int n_in,
                              void* d_out, int out_size)
{
    (void)in_sizes; (void)n_in; (void)out_size;
    const float* x     = (const float*)d_in[0];
    const float* wv    = (const float*)d_in[1];
    const float* wq    = (const float*)d_in[2];
    const float* wk    = (const float*)d_in[3];
    const float* gamma = (const float*)d_in[4];
    const float* beta  = (const float*)d_in[5];
    const float* mean  = (const float*)d_in[6];
    const float* var   = (const float*)d_in[7];
    float* out = (float*)d_out;

    qkv_proj_kernel<<<dim3(32, 3, B_), 256>>>(x, wv, wq, wk);
    retile_qk_kernel<<<dim3(64, 2, B_), 256>>>();
    vtrans_kernel<<<dim3(64, 4, B_), 256>>>();
    cudaFuncSetAttribute(attn_kernel, cudaFuncAttributeMaxDynamicSharedMemorySize, SMEM_SZ);
    attn_kernel<<<dim3(64, B_), 256, SMEM_SZ>>>(x, gamma, beta, mean, var, out);
}